// round 8
// baseline (speedup 1.0000x reference)
#include <cuda_runtime.h>
#include <cuda_bf16.h>

#define NN 50000
#define NE 800000
#define CIN 128
#define CHID 128
#define COUT 64

// ---------------- scratch (static device globals; no allocs allowed) ----------------
// NOTE: these symbols are ONLY referenced (a) inside device code, (b) via
// cudaGetSymbolAddress in host code. Never passed by name from host code —
// that is a host-compile error and was silently wedging the build.
__device__ __align__(16) float g_deg[NN];
__device__ __align__(16) float g_dinv[NN];
__device__ __align__(16) float g_hW[(size_t)NN * CHID];    // x @ W1
__device__ __align__(16) float g_agg1[(size_t)NN * CHID];  // conv1 agg -> h (post relu)
__device__ __align__(16) float g_z0[(size_t)NN * COUT];    // h @ W2
__device__ __align__(16) float g_agg2[(size_t)NN * COUT];  // conv2 agg -> z
__device__ __align__(16) float g_u[(size_t)NN * COUT];     // z @ Wb
__device__ int g_is64;

// Emulate XLA-on-GPU f32 dot_general (BF16_BF16_F32 algorithm): both operands
// rounded to bf16 (RNE), accumulate in f32.
__device__ __forceinline__ float bfq(float x) {
    return __bfloat162float(__float2bfloat16_rn(x));
}

__device__ __forceinline__ int eidx(const void* ei, unsigned idx, int is64) {
    if (is64) return (int)((const long long*)ei)[idx];
    return ((const int*)ei)[idx];
}

// ---------------- setup: probe dtype, init deg, zero agg buffers ----------------
__global__ void k_setup(const int* __restrict__ ei32, float* __restrict__ deg,
                        float* __restrict__ agg1, float* __restrict__ agg2,
                        int* __restrict__ is64p) {
    int i = blockIdx.x * blockDim.x + threadIdx.x;
    if (i == 0) {
        // int64 edge data with values < 2^31: every odd little-endian word is 0.
        // 64 consecutive zero int32 edge ids has probability ~0.
        int is64 = 1;
        for (int k = 1; k < 128; k += 2)
            if (ei32[k] != 0) { is64 = 0; break; }
        *is64p = is64;
    }
    if (i < NN) deg[i] = 1.0f;  // self loop
    int stride = gridDim.x * blockDim.x;
    for (int j = i; j < NN * CHID / 4; j += stride)
        ((float4*)agg1)[j] = make_float4(0.f, 0.f, 0.f, 0.f);
    for (int j = i; j < NN * COUT / 4; j += stride)
        ((float4*)agg2)[j] = make_float4(0.f, 0.f, 0.f, 0.f);
}

__global__ void k_degree(const void* __restrict__ ei, float* __restrict__ deg,
                         const int* __restrict__ is64p) {
    int e = blockIdx.x * blockDim.x + threadIdx.x;
    if (e < NE) atomicAdd(&deg[eidx(ei, NE + e, *is64p)], 1.0f);
}

__global__ void k_dinv(const float* __restrict__ deg, float* __restrict__ dinv) {
    int i = blockIdx.x * blockDim.x + threadIdx.x;
    if (i < NN) dinv[i] = rsqrtf(deg[i]);
}

// ------- GEMM with bf16-rounded operands, f32 accumulate: out = A[NN,K] @ W[K,NC] -------
template <int K, int NC>
__global__ void k_gemm(const float* __restrict__ A, const float* __restrict__ W,
                       float* __restrict__ out) {
    constexpr int ROWS = 8;
    __shared__ float As[ROWS][K];
    int r0 = blockIdx.x * ROWS;
    int c = threadIdx.x;  // blockDim.x == NC
    for (int idx = c; idx < ROWS * K; idx += NC) {
        int r = idx / K;
        int k = idx - r * K;
        int gr = r0 + r;
        As[r][k] = (gr < NN) ? bfq(A[(size_t)gr * K + k]) : 0.f;
    }
    __syncthreads();
    float acc[ROWS];
#pragma unroll
    for (int r = 0; r < ROWS; r++) acc[r] = 0.f;
#pragma unroll 4
    for (int k = 0; k < K; k++) {
        float w = bfq(W[k * NC + c]);
#pragma unroll
        for (int r = 0; r < ROWS; r++) acc[r] = fmaf(As[r][k], w, acc[r]);
    }
#pragma unroll
    for (int r = 0; r < ROWS; r++) {
        int gr = r0 + r;
        if (gr < NN) out[(size_t)gr * NC + c] = acc[r];
    }
}

// ------- edge scatter: agg[dst] += h[src] * dinv[src]*dinv[dst] (exact f32) -------
__global__ void k_push128(const void* __restrict__ ei, const float* __restrict__ h,
                          float* __restrict__ agg, const float* __restrict__ dinv,
                          const int* __restrict__ is64p) {
    unsigned t = blockIdx.x * blockDim.x + threadIdx.x;
    unsigned e = t >> 5;
    int lane = t & 31;
    if (e >= NE) return;
    int is64 = *is64p;
    int s = eidx(ei, e, is64);
    int d = eidx(ei, NE + e, is64);
    float w = dinv[s] * dinv[d];
    float4 v = ((const float4*)(h + (size_t)s * CHID))[lane];
    float* p = agg + (size_t)d * CHID + lane * 4;
    asm volatile("red.global.add.v4.f32 [%0], {%1,%2,%3,%4};"
                 :: "l"(p), "f"(v.x * w), "f"(v.y * w), "f"(v.z * w), "f"(v.w * w)
                 : "memory");
}

__global__ void k_push64(const void* __restrict__ ei, const float* __restrict__ h,
                         float* __restrict__ agg, const float* __restrict__ dinv,
                         const int* __restrict__ is64p) {
    unsigned t = blockIdx.x * blockDim.x + threadIdx.x;
    unsigned e = t >> 4;
    int lane = t & 15;
    if (e >= NE) return;
    int is64 = *is64p;
    int s = eidx(ei, e, is64);
    int d = eidx(ei, NE + e, is64);
    float w = dinv[s] * dinv[d];
    float4 v = ((const float4*)(h + (size_t)s * COUT))[lane];
    float* p = agg + (size_t)d * COUT + lane * 4;
    asm volatile("red.global.add.v4.f32 [%0], {%1,%2,%3,%4};"
                 :: "l"(p), "f"(v.x * w), "f"(v.y * w), "f"(v.z * w), "f"(v.w * w)
                 : "memory");
}

// ------- finalize: agg += pre * (1/deg) + b; optional relu (exact f32) -------
template <int C, bool RELU>
__global__ void k_post(float* __restrict__ agg, const float* __restrict__ pre,
                       const float* __restrict__ b, const float* __restrict__ deg) {
    constexpr int C4 = C / 4;
    unsigned t = blockIdx.x * blockDim.x + threadIdx.x;
    if (t >= (unsigned)NN * C4) return;
    unsigned i = t / C4;
    unsigned c4 = t - i * C4;
    float sw = 1.0f / deg[i];
    float4 a = ((const float4*)agg)[t];
    float4 p = ((const float4*)pre)[t];
    float4 bv = ((const float4*)b)[c4];
    float4 o;
    o.x = fmaf(p.x, sw, a.x) + bv.x;
    o.y = fmaf(p.y, sw, a.y) + bv.y;
    o.z = fmaf(p.z, sw, a.z) + bv.z;
    o.w = fmaf(p.w, sw, a.w) + bv.w;
    if (RELU) {
        o.x = fmaxf(o.x, 0.f); o.y = fmaxf(o.y, 0.f);
        o.z = fmaxf(o.z, 0.f); o.w = fmaxf(o.w, 0.f);
    }
    ((float4*)agg)[t] = o;
}

// ------- decode: out[e] = sigmoid(dot(bf16(u[src]), bf16(z[dst])) + bb) -------
__global__ void k_edges(const void* __restrict__ ei, const float* __restrict__ u,
                        const float* __restrict__ z, const float* __restrict__ bb,
                        float* __restrict__ out, const int* __restrict__ is64p) {
    unsigned t = blockIdx.x * blockDim.x + threadIdx.x;
    unsigned e = t >> 4;
    int lane = t & 15;
    if (e >= NE) return;
    int is64 = *is64p;
    int s = eidx(ei, e, is64);
    int d = eidx(ei, NE + e, is64);
    float4 a = ((const float4*)(u + (size_t)s * COUT))[lane];
    float4 b = ((const float4*)(z + (size_t)d * COUT))[lane];
    float p = bfq(a.x) * bfq(b.x) + bfq(a.y) * bfq(b.y)
            + bfq(a.z) * bfq(b.z) + bfq(a.w) * bfq(b.w);
    p += __shfl_xor_sync(0xffffffffu, p, 8);
    p += __shfl_xor_sync(0xffffffffu, p, 4);
    p += __shfl_xor_sync(0xffffffffu, p, 2);
    p += __shfl_xor_sync(0xffffffffu, p, 1);
    if (lane == 0) out[e] = 1.f / (1.f + expf(-(p + bb[0])));
}

extern "C" void kernel_launch(void* const* d_in, const int* in_sizes, int n_in,
                              void* d_out, int out_size) {
    const float* x  = (const float*)d_in[0];
    const void* ei  = d_in[1];  // int32 or int64, probed on device
    const float* W1 = (const float*)d_in[2];
    const float* b1 = (const float*)d_in[3];
    const float* W2 = (const float*)d_in[4];
    const float* b2 = (const float*)d_in[5];
    const float* Wb = (const float*)d_in[6];
    const float* bb = (const float*)d_in[7];
    float* out      = (float*)d_out;

    // Legal host-side access to device globals: symbol API only.
    float *deg, *dinv, *hW, *agg1, *z0, *agg2, *u;
    int* is64p;
    cudaGetSymbolAddress((void**)&deg,  g_deg);
    cudaGetSymbolAddress((void**)&dinv, g_dinv);
    cudaGetSymbolAddress((void**)&hW,   g_hW);
    cudaGetSymbolAddress((void**)&agg1, g_agg1);
    cudaGetSymbolAddress((void**)&z0,   g_z0);
    cudaGetSymbolAddress((void**)&agg2, g_agg2);
    cudaGetSymbolAddress((void**)&u,    g_u);
    cudaGetSymbolAddress((void**)&is64p, g_is64);

    const int T = 256;
    k_setup<<<(NN + T - 1) / T, T>>>((const int*)ei, deg, agg1, agg2, is64p);
    k_degree<<<(NE + T - 1) / T, T>>>(ei, deg, is64p);
    k_dinv<<<(NN + T - 1) / T, T>>>(deg, dinv);

    // conv1: bf16-operand GEMM, exact-f32 aggregation
    k_gemm<CIN, CHID><<<(NN + 7) / 8, CHID>>>(x, W1, hW);
    k_push128<<<(NE * 32 + T - 1) / T, T>>>(ei, hW, agg1, dinv, is64p);
    k_post<CHID, true><<<(NN * (CHID / 4) + T - 1) / T, T>>>(agg1, hW, b1, deg);

    // conv2
    k_gemm<CHID, COUT><<<(NN + 7) / 8, COUT>>>(agg1, W2, z0);
    k_push64<<<(NE * 16 + T - 1) / T, T>>>(ei, z0, agg2, dinv, is64p);
    k_post<COUT, false><<<(NN * (COUT / 4) + T - 1) / T, T>>>(agg2, z0, b2, deg);

    // decoder: u = z @ Wb (bf16 operands), then per-edge bf16-operand dot + sigmoid
    k_gemm<COUT, COUT><<<(NN + 7) / 8, COUT>>>(agg2, Wb, u);
    k_edges<<<(NE * 16 + T - 1) / T, T>>>(ei, u, agg2, bb, out, is64p);
}

// round 9
// speedup vs baseline: 1.1798x; 1.1798x over previous
#include <cuda_runtime.h>
#include <cuda_bf16.h>
#include <mma.h>
using namespace nvcuda;

#define NN 50000
#define NN_PAD 50048   // 782 * 64, multiple of the 64-row GEMM block tile
#define NE 800000
#define CIN 128
#define CHID 128
#define COUT 64

// ---------------- scratch (static device globals; no allocs allowed) ----------------
// Host code touches these ONLY via cudaGetSymbolAddress.
__device__ __align__(16) float g_deg[NN];
__device__ __align__(16) float g_dinv[NN];
__device__ __align__(16) __nv_bfloat16 g_xb[(size_t)NN_PAD * CIN];   // bf16(x), pad rows 0
__device__ __align__(16) __nv_bfloat16 g_W1b[CIN * CHID];
__device__ __align__(16) __nv_bfloat16 g_W2b[CHID * COUT];
__device__ __align__(16) __nv_bfloat16 g_Wbb[COUT * COUT];
__device__ __align__(16) float g_hW[(size_t)NN_PAD * CHID];          // x @ W1 (f32)
__device__ __align__(16) float g_agg1[(size_t)NN * CHID];            // conv1 aggregation
__device__ __align__(16) __nv_bfloat16 g_hb[(size_t)NN_PAD * CHID];  // bf16(relu h), pad 0
__device__ __align__(16) float g_z0[(size_t)NN_PAD * COUT];          // h @ W2 (f32)
__device__ __align__(16) float g_agg2[(size_t)NN * COUT];            // conv2 aggregation
__device__ __align__(16) __nv_bfloat16 g_zb[(size_t)NN_PAD * COUT];  // bf16(z), pad 0
__device__ __align__(16) float g_u[(size_t)NN_PAD * COUT];           // z @ Wb (f32)
__device__ __align__(16) __nv_bfloat16 g_ub[(size_t)NN_PAD * COUT];  // bf16(u)
__device__ int g_is64;

__device__ __forceinline__ int eidx(const void* ei, unsigned idx, int is64) {
    if (is64) return (int)((const long long*)ei)[idx];
    return ((const int*)ei)[idx];
}

// ---------------- setup: probe dtype, init deg, zero agg buffers ----------------
__global__ void k_setup(const int* __restrict__ ei32, float* __restrict__ deg,
                        float* __restrict__ agg1, float* __restrict__ agg2,
                        int* __restrict__ is64p) {
    int i = blockIdx.x * blockDim.x + threadIdx.x;
    if (i == 0) {
        int is64 = 1;
        for (int k = 1; k < 128; k += 2)
            if (ei32[k] != 0) { is64 = 0; break; }
        *is64p = is64;
    }
    if (i < NN) deg[i] = 1.0f;  // self loop
    int stride = gridDim.x * blockDim.x;
    for (int j = i; j < NN * CHID / 4; j += stride)
        ((float4*)agg1)[j] = make_float4(0.f, 0.f, 0.f, 0.f);
    for (int j = i; j < NN * COUT / 4; j += stride)
        ((float4*)agg2)[j] = make_float4(0.f, 0.f, 0.f, 0.f);
}

__global__ void k_degree(const void* __restrict__ ei, float* __restrict__ deg,
                         const int* __restrict__ is64p) {
    int e = blockIdx.x * blockDim.x + threadIdx.x;
    if (e < NE) atomicAdd(&deg[eidx(ei, NE + e, *is64p)], 1.0f);
}

__global__ void k_dinv(const float* __restrict__ deg, float* __restrict__ dinv) {
    int i = blockIdx.x * blockDim.x + threadIdx.x;
    if (i < NN) dinv[i] = rsqrtf(deg[i]);
}

// ---------------- f32 -> bf16 conversion (pad region -> 0) ----------------
__global__ void k_cvt(const float* __restrict__ src, __nv_bfloat16* __restrict__ dst,
                      int n_valid, int n_total) {
    int i = blockIdx.x * blockDim.x + threadIdx.x;
    if (i < n_total) dst[i] = (i < n_valid) ? __float2bfloat16_rn(src[i]) : __float2bfloat16_rn(0.f);
}

__global__ void k_cvtW(const float* __restrict__ W1, const float* __restrict__ W2,
                       const float* __restrict__ Wb, __nv_bfloat16* __restrict__ W1b,
                       __nv_bfloat16* __restrict__ W2b, __nv_bfloat16* __restrict__ Wbb) {
    int i = blockIdx.x * blockDim.x + threadIdx.x;
    if (i < CIN * CHID) W1b[i] = __float2bfloat16_rn(W1[i]);
    if (i < CHID * COUT) W2b[i] = __float2bfloat16_rn(W2[i]);
    if (i < COUT * COUT) Wbb[i] = __float2bfloat16_rn(Wb[i]);
}

// ------- tensor-core GEMM: out[NN_PAD,NC] = A[NN_PAD,K](bf16) @ W[K,NC](bf16), f32 accum -------
// block = 4 warps, 64 rows; W cached in smem.
template <int K, int NC>
__global__ void k_wgemm(const __nv_bfloat16* __restrict__ A,
                        const __nv_bfloat16* __restrict__ W,
                        float* __restrict__ out) {
    __shared__ __nv_bfloat16 Ws[K * NC];
    int tid = threadIdx.x;
    for (int i = tid * 8; i < K * NC; i += blockDim.x * 8)
        *(uint4*)(Ws + i) = *(const uint4*)(W + i);
    __syncthreads();
    int warp = tid >> 5;
    size_t row0 = (size_t)blockIdx.x * 64 + warp * 16;
    wmma::fragment<wmma::accumulator, 16, 16, 16, float> acc[NC / 16];
#pragma unroll
    for (int n = 0; n < NC / 16; n++) wmma::fill_fragment(acc[n], 0.f);
#pragma unroll
    for (int k0 = 0; k0 < K; k0 += 16) {
        wmma::fragment<wmma::matrix_a, 16, 16, 16, __nv_bfloat16, wmma::row_major> af;
        wmma::load_matrix_sync(af, A + row0 * K + k0, K);
#pragma unroll
        for (int n = 0; n < NC / 16; n++) {
            wmma::fragment<wmma::matrix_b, 16, 16, 16, __nv_bfloat16, wmma::row_major> bf;
            wmma::load_matrix_sync(bf, Ws + k0 * NC + n * 16, NC);
            wmma::mma_sync(acc[n], af, bf, acc[n]);
        }
    }
#pragma unroll
    for (int n = 0; n < NC / 16; n++)
        wmma::store_matrix_sync(out + row0 * NC + n * 16, acc[n], NC, wmma::mem_row_major);
}

// ------- edge scatter: agg[dst] += h[src] * dinv[src]*dinv[dst] (exact f32) -------
__global__ void k_push128(const void* __restrict__ ei, const float* __restrict__ h,
                          float* __restrict__ agg, const float* __restrict__ dinv,
                          const int* __restrict__ is64p) {
    unsigned t = blockIdx.x * blockDim.x + threadIdx.x;
    unsigned e = t >> 5;
    int lane = t & 31;
    if (e >= NE) return;
    int is64 = *is64p;
    int s = eidx(ei, e, is64);
    int d = eidx(ei, NE + e, is64);
    float w = dinv[s] * dinv[d];
    float4 v = ((const float4*)(h + (size_t)s * CHID))[lane];
    float* p = agg + (size_t)d * CHID + lane * 4;
    asm volatile("red.global.add.v4.f32 [%0], {%1,%2,%3,%4};"
                 :: "l"(p), "f"(v.x * w), "f"(v.y * w), "f"(v.z * w), "f"(v.w * w)
                 : "memory");
}

__global__ void k_push64(const void* __restrict__ ei, const float* __restrict__ h,
                         float* __restrict__ agg, const float* __restrict__ dinv,
                         const int* __restrict__ is64p) {
    unsigned t = blockIdx.x * blockDim.x + threadIdx.x;
    unsigned e = t >> 4;
    int lane = t & 15;
    if (e >= NE) return;
    int is64 = *is64p;
    int s = eidx(ei, e, is64);
    int d = eidx(ei, NE + e, is64);
    float w = dinv[s] * dinv[d];
    float4 v = ((const float4*)(h + (size_t)s * COUT))[lane];
    float* p = agg + (size_t)d * COUT + lane * 4;
    asm volatile("red.global.add.v4.f32 [%0], {%1,%2,%3,%4};"
                 :: "l"(p), "f"(v.x * w), "f"(v.y * w), "f"(v.z * w), "f"(v.w * w)
                 : "memory");
}

// ------- finalize: bf16( relu?( agg + pre*(1/deg) + b ) ) — bf16 is the only consumer -------
template <int C, bool RELU>
__global__ void k_post(const float* __restrict__ agg, const float* __restrict__ pre,
                       const float* __restrict__ b, const float* __restrict__ deg,
                       __nv_bfloat16* __restrict__ bout) {
    constexpr int C4 = C / 4;
    unsigned t = blockIdx.x * blockDim.x + threadIdx.x;
    if (t >= (unsigned)NN * C4) return;
    unsigned i = t / C4;
    unsigned c4 = t - i * C4;
    float sw = 1.0f / deg[i];
    float4 a = ((const float4*)agg)[t];
    float4 p = ((const float4*)pre)[t];
    float4 bv = ((const float4*)b)[c4];
    float4 o;
    o.x = fmaf(p.x, sw, a.x) + bv.x;
    o.y = fmaf(p.y, sw, a.y) + bv.y;
    o.z = fmaf(p.z, sw, a.z) + bv.z;
    o.w = fmaf(p.w, sw, a.w) + bv.w;
    if (RELU) {
        o.x = fmaxf(o.x, 0.f); o.y = fmaxf(o.y, 0.f);
        o.z = fmaxf(o.z, 0.f); o.w = fmaxf(o.w, 0.f);
    }
    __nv_bfloat162 lo = __floats2bfloat162_rn(o.x, o.y);
    __nv_bfloat162 hi = __floats2bfloat162_rn(o.z, o.w);
    ((__nv_bfloat162*)bout)[t * 2]     = lo;
    ((__nv_bfloat162*)bout)[t * 2 + 1] = hi;
}

// ------- decode: out[e] = sigmoid(dot(u_bf16[src], z_bf16[dst]) + bb), 8 lanes/edge -------
__global__ void k_edges(const void* __restrict__ ei, const __nv_bfloat16* __restrict__ ub,
                        const __nv_bfloat16* __restrict__ zb, const float* __restrict__ bb,
                        float* __restrict__ out, const int* __restrict__ is64p) {
    unsigned t = blockIdx.x * blockDim.x + threadIdx.x;
    unsigned e = t >> 3;
    int lane = t & 7;
    if (e >= NE) return;
    int is64 = *is64p;
    int s = eidx(ei, e, is64);
    int d = eidx(ei, NE + e, is64);
    const __nv_bfloat162* ap = (const __nv_bfloat162*)(ub + (size_t)s * COUT) + lane * 4;
    const __nv_bfloat162* bp = (const __nv_bfloat162*)(zb + (size_t)d * COUT) + lane * 4;
    float p = 0.f;
#pragma unroll
    for (int j = 0; j < 4; j++) {
        float2 fa = __bfloat1622float2(ap[j]);
        float2 fb = __bfloat1622float2(bp[j]);
        p = fmaf(fa.x, fb.x, p);
        p = fmaf(fa.y, fb.y, p);
    }
    p += __shfl_xor_sync(0xffffffffu, p, 4);
    p += __shfl_xor_sync(0xffffffffu, p, 2);
    p += __shfl_xor_sync(0xffffffffu, p, 1);
    if (lane == 0) out[e] = 1.f / (1.f + expf(-(p + bb[0])));
}

extern "C" void kernel_launch(void* const* d_in, const int* in_sizes, int n_in,
                              void* d_out, int out_size) {
    const float* x  = (const float*)d_in[0];
    const void* ei  = d_in[1];  // int32 or int64, probed on device
    const float* W1 = (const float*)d_in[2];
    const float* b1 = (const float*)d_in[3];
    const float* W2 = (const float*)d_in[4];
    const float* b2 = (const float*)d_in[5];
    const float* Wb = (const float*)d_in[6];
    const float* bb = (const float*)d_in[7];
    float* out      = (float*)d_out;

    float *deg, *dinv, *hW, *agg1, *z0, *agg2, *u;
    __nv_bfloat16 *xb, *W1b, *W2b, *Wbb, *hb, *zb, *ub;
    int* is64p;
    cudaGetSymbolAddress((void**)&deg,  g_deg);
    cudaGetSymbolAddress((void**)&dinv, g_dinv);
    cudaGetSymbolAddress((void**)&xb,   g_xb);
    cudaGetSymbolAddress((void**)&W1b,  g_W1b);
    cudaGetSymbolAddress((void**)&W2b,  g_W2b);
    cudaGetSymbolAddress((void**)&Wbb,  g_Wbb);
    cudaGetSymbolAddress((void**)&hW,   g_hW);
    cudaGetSymbolAddress((void**)&agg1, g_agg1);
    cudaGetSymbolAddress((void**)&hb,   g_hb);
    cudaGetSymbolAddress((void**)&z0,   g_z0);
    cudaGetSymbolAddress((void**)&agg2, g_agg2);
    cudaGetSymbolAddress((void**)&zb,   g_zb);
    cudaGetSymbolAddress((void**)&u,    g_u);
    cudaGetSymbolAddress((void**)&ub,   g_ub);
    cudaGetSymbolAddress((void**)&is64p, g_is64);

    const int T = 256;
    k_setup<<<(NN + T - 1) / T, T>>>((const int*)ei, deg, agg1, agg2, is64p);
    k_degree<<<(NE + T - 1) / T, T>>>(ei, deg, is64p);
    k_dinv<<<(NN + T - 1) / T, T>>>(deg, dinv);
    k_cvt<<<(NN_PAD * CIN + T - 1) / T, T>>>(x, xb, NN * CIN, NN_PAD * CIN);
    k_cvtW<<<(CIN * CHID + T - 1) / T, T>>>(W1, W2, Wb, W1b, W2b, Wbb);

    // conv1: tensor-core GEMM (bf16 operands, f32 accum) + exact-f32 aggregation
    k_wgemm<CIN, CHID><<<NN_PAD / 64, 128>>>(xb, W1b, hW);
    k_push128<<<(NE * 32 + T - 1) / T, T>>>(ei, hW, agg1, dinv, is64p);
    k_post<CHID, true><<<(NN * (CHID / 4) + T - 1) / T, T>>>(agg1, hW, b1, deg, hb);

    // conv2
    k_wgemm<CHID, COUT><<<NN_PAD / 64, 128>>>(hb, W2b, z0);
    k_push64<<<(NE * 16 + T - 1) / T, T>>>(ei, z0, agg2, dinv, is64p);
    k_post<COUT, false><<<(NN * (COUT / 4) + T - 1) / T, T>>>(agg2, z0, b2, deg, zb);

    // decoder: u = z @ Wb, then per-edge bf16 dot + sigmoid
    k_wgemm<COUT, COUT><<<NN_PAD / 64, 128>>>(zb, Wbb, u);
    k_cvt<<<(NN_PAD * COUT + T - 1) / T, T>>>(u, ub, NN_PAD * COUT, NN_PAD * COUT);
    k_edges<<<(NE * 8 + T - 1) / T, T>>>(ei, ub, zb, bb, out, is64p);
}

// round 10
// speedup vs baseline: 1.7079x; 1.4476x over previous
#include <cuda_runtime.h>
#include <cuda_bf16.h>
#include <mma.h>
using namespace nvcuda;

#define NN 50000
#define NN_PAD 50048   // 782 * 64
#define NE 800000
#define CIN 128
#define CHID 128
#define COUT 64
#define NB 196         // ceil(NN/256)

// ---------------- scratch (static device globals; host uses cudaGetSymbolAddress) ----------------
__device__ __align__(16) int   g_cnt[NN];      // in-degree (edges only)
__device__ __align__(16) int   g_fpos[NN];     // fill cursor
__device__ __align__(16) int   g_tmp[NN];      // block-local exclusive scan
__device__ __align__(16) int   g_bsum[256];    // per-block sums
__device__ __align__(16) int   g_rp[NN];       // CSR row_ptr
__device__ __align__(16) int   g_csr[NE];      // CSR src ids
__device__ __align__(16) float g_dinv[NN];     // 1/sqrt(deg)
__device__ __align__(16) float g_invdeg[NN];   // exact 1/deg
__device__ __align__(16) __nv_bfloat16 g_xb[(size_t)NN_PAD * CIN];
__device__ __align__(16) __nv_bfloat16 g_W1b[CIN * CHID];
__device__ __align__(16) __nv_bfloat16 g_W2b[CHID * COUT];
__device__ __align__(16) __nv_bfloat16 g_Wbb[COUT * COUT];
__device__ __align__(16) float g_hW[(size_t)NN_PAD * CHID];          // x @ W1
__device__ __align__(16) __nv_bfloat16 g_hb[(size_t)NN_PAD * CHID];  // bf16(relu h); pad stays 0
__device__ __align__(16) float g_z0[(size_t)NN_PAD * COUT];          // h @ W2
__device__ __align__(16) __nv_bfloat16 g_zb[(size_t)NN_PAD * COUT];  // bf16(z); pad stays 0
__device__ __align__(16) float g_u[(size_t)NN_PAD * COUT];           // z @ Wb
__device__ __align__(16) __nv_bfloat16 g_ub[(size_t)NN_PAD * COUT];
__device__ int g_is64;

__device__ __forceinline__ int eidx(const void* ei, unsigned idx, int is64) {
    if (is64) return (int)((const long long*)ei)[idx];
    return ((const int*)ei)[idx];
}

// ---------------- setup: probe dtype, zero counters ----------------
__global__ void k_setup(const int* __restrict__ ei32, int* __restrict__ cnt,
                        int* __restrict__ fpos, int* __restrict__ is64p) {
    int i = blockIdx.x * blockDim.x + threadIdx.x;
    if (i == 0) {
        int is64 = 1;
        for (int k = 1; k < 128; k += 2)
            if (ei32[k] != 0) { is64 = 0; break; }
        *is64p = is64;
    }
    if (i < NN) { cnt[i] = 0; fpos[i] = 0; }
}

__global__ void k_count(const void* __restrict__ ei, int* __restrict__ cnt,
                        const int* __restrict__ is64p) {
    int e = blockIdx.x * blockDim.x + threadIdx.x;
    if (e < NE) atomicAdd(&cnt[eidx(ei, NE + e, *is64p)], 1);
}

__global__ void k_dinv(const int* __restrict__ cnt, float* __restrict__ dinv,
                       float* __restrict__ invdeg) {
    int i = blockIdx.x * blockDim.x + threadIdx.x;
    if (i < NN) {
        float deg = (float)(cnt[i] + 1);  // +1 self loop
        dinv[i] = rsqrtf(deg);
        invdeg[i] = 1.0f / deg;
    }
}

// ---------------- exclusive scan over cnt -> rp (3 phases) ----------------
__global__ void k_scan1(const int* __restrict__ cnt, int* __restrict__ tmp,
                        int* __restrict__ bsum) {
    __shared__ int sh[256];
    int i = blockIdx.x * 256 + threadIdx.x;
    int v = (i < NN) ? cnt[i] : 0;
    sh[threadIdx.x] = v;
    __syncthreads();
    for (int off = 1; off < 256; off <<= 1) {
        int t = (threadIdx.x >= off) ? sh[threadIdx.x - off] : 0;
        __syncthreads();
        sh[threadIdx.x] += t;
        __syncthreads();
    }
    if (i < NN) tmp[i] = sh[threadIdx.x] - v;  // exclusive
    if (threadIdx.x == 255) bsum[blockIdx.x] = sh[255];
}

__global__ void k_scan2(int* __restrict__ bsum) {
    __shared__ int sh[256];
    int v = (threadIdx.x < NB) ? bsum[threadIdx.x] : 0;
    sh[threadIdx.x] = v;
    __syncthreads();
    for (int off = 1; off < 256; off <<= 1) {
        int t = (threadIdx.x >= off) ? sh[threadIdx.x - off] : 0;
        __syncthreads();
        sh[threadIdx.x] += t;
        __syncthreads();
    }
    if (threadIdx.x < NB) bsum[threadIdx.x] = sh[threadIdx.x] - v;  // exclusive
}

__global__ void k_scan3(const int* __restrict__ tmp, const int* __restrict__ bsum,
                        int* __restrict__ rp) {
    int i = blockIdx.x * 256 + threadIdx.x;
    if (i < NN) rp[i] = tmp[i] + bsum[i >> 8];
}

__global__ void k_fill(const void* __restrict__ ei, const int* __restrict__ rp,
                       int* __restrict__ fpos, int* __restrict__ csr,
                       const int* __restrict__ is64p) {
    int e = blockIdx.x * blockDim.x + threadIdx.x;
    if (e >= NE) return;
    int is64 = *is64p;
    int s = eidx(ei, e, is64);
    int d = eidx(ei, NE + e, is64);
    int pos = rp[d] + atomicAdd(&fpos[d], 1);
    csr[pos] = s;
}

// ---------------- conversions ----------------
// 8 elems/thread; n_valid and n_total divisible by 8
__global__ void k_cvt8(const float* __restrict__ src, __nv_bfloat16* __restrict__ dst,
                       int n_valid, int n_total) {
    int base = (blockIdx.x * blockDim.x + threadIdx.x) * 8;
    if (base >= n_total) return;
    uint4 o;
    if (base < n_valid) {
        float4 a = *(const float4*)(src + base);
        float4 b = *(const float4*)(src + base + 4);
        __nv_bfloat162 p0 = __floats2bfloat162_rn(a.x, a.y);
        __nv_bfloat162 p1 = __floats2bfloat162_rn(a.z, a.w);
        __nv_bfloat162 p2 = __floats2bfloat162_rn(b.x, b.y);
        __nv_bfloat162 p3 = __floats2bfloat162_rn(b.z, b.w);
        o.x = *(unsigned*)&p0; o.y = *(unsigned*)&p1;
        o.z = *(unsigned*)&p2; o.w = *(unsigned*)&p3;
    } else {
        o = make_uint4(0, 0, 0, 0);
    }
    *(uint4*)(dst + base) = o;
}

__global__ void k_cvtW(const float* __restrict__ W1, const float* __restrict__ W2,
                       const float* __restrict__ Wb, __nv_bfloat16* __restrict__ W1b,
                       __nv_bfloat16* __restrict__ W2b, __nv_bfloat16* __restrict__ Wbb) {
    int i = blockIdx.x * blockDim.x + threadIdx.x;
    if (i < CIN * CHID) W1b[i] = __float2bfloat16_rn(W1[i]);
    if (i < CHID * COUT) W2b[i] = __float2bfloat16_rn(W2[i]);
    if (i < COUT * COUT) Wbb[i] = __float2bfloat16_rn(Wb[i]);
}

// ------- tensor-core GEMM: out[NN_PAD,NC] = A(bf16) @ W(bf16), f32 accum -------
template <int K, int NC>
__global__ void k_wgemm(const __nv_bfloat16* __restrict__ A,
                        const __nv_bfloat16* __restrict__ W,
                        float* __restrict__ out) {
    __shared__ __nv_bfloat16 Ws[K * NC];
    int tid = threadIdx.x;
    for (int i = tid * 8; i < K * NC; i += blockDim.x * 8)
        *(uint4*)(Ws + i) = *(const uint4*)(W + i);
    __syncthreads();
    int warp = tid >> 5;
    size_t row0 = (size_t)blockIdx.x * 64 + warp * 16;
    wmma::fragment<wmma::accumulator, 16, 16, 16, float> acc[NC / 16];
#pragma unroll
    for (int n = 0; n < NC / 16; n++) wmma::fill_fragment(acc[n], 0.f);
#pragma unroll
    for (int k0 = 0; k0 < K; k0 += 16) {
        wmma::fragment<wmma::matrix_a, 16, 16, 16, __nv_bfloat16, wmma::row_major> af;
        wmma::load_matrix_sync(af, A + row0 * K + k0, K);
#pragma unroll
        for (int n = 0; n < NC / 16; n++) {
            wmma::fragment<wmma::matrix_b, 16, 16, 16, __nv_bfloat16, wmma::row_major> bf;
            wmma::load_matrix_sync(bf, Ws + k0 * NC + n * 16, NC);
            wmma::mma_sync(acc[n], af, bf, acc[n]);
        }
    }
#pragma unroll
    for (int n = 0; n < NC / 16; n++)
        wmma::store_matrix_sync(out + row0 * NC + n * 16, acc[n], NC, wmma::mem_row_major);
}

// ------- CSR gather + finalize, 128ch: one warp per node -------
// hb[i] = bf16( relu( sum_j hW[src_j]*dinv[src_j]*dinv[i] + hW[i]*invdeg[i] + b1 ) )
__global__ void k_gather128(const int* __restrict__ rp, const int* __restrict__ cnt,
                            const int* __restrict__ csr, const float* __restrict__ hW,
                            const float* __restrict__ dinv, const float* __restrict__ invdeg,
                            const float* __restrict__ b, __nv_bfloat16* __restrict__ bout) {
    int warp = (blockIdx.x * blockDim.x + threadIdx.x) >> 5;
    int lane = threadIdx.x & 31;
    if (warp >= NN) return;
    int node = warp;
    int n = cnt[node];
    int base = rp[node];
    float dd = dinv[node];
    float4 acc = make_float4(0.f, 0.f, 0.f, 0.f);
    int j = 0;
    for (; j + 2 <= n; j += 2) {
        int s0 = csr[base + j];
        int s1 = csr[base + j + 1];
        float w0 = dinv[s0] * dd;
        float w1 = dinv[s1] * dd;
        float4 v0 = ((const float4*)(hW + (size_t)s0 * CHID))[lane];
        float4 v1 = ((const float4*)(hW + (size_t)s1 * CHID))[lane];
        acc.x += v0.x * w0 + v1.x * w1;
        acc.y += v0.y * w0 + v1.y * w1;
        acc.z += v0.z * w0 + v1.z * w1;
        acc.w += v0.w * w0 + v1.w * w1;
    }
    if (j < n) {
        int s0 = csr[base + j];
        float w0 = dinv[s0] * dd;
        float4 v0 = ((const float4*)(hW + (size_t)s0 * CHID))[lane];
        acc.x += v0.x * w0; acc.y += v0.y * w0;
        acc.z += v0.z * w0; acc.w += v0.w * w0;
    }
    float idg = invdeg[node];
    float4 p = ((const float4*)(hW + (size_t)node * CHID))[lane];
    float4 bv = ((const float4*)b)[lane];
    float ox = fmaxf(fmaf(p.x, idg, acc.x) + bv.x, 0.f);
    float oy = fmaxf(fmaf(p.y, idg, acc.y) + bv.y, 0.f);
    float oz = fmaxf(fmaf(p.z, idg, acc.z) + bv.z, 0.f);
    float ow = fmaxf(fmaf(p.w, idg, acc.w) + bv.w, 0.f);
    __nv_bfloat162 lo = __floats2bfloat162_rn(ox, oy);
    __nv_bfloat162 hi = __floats2bfloat162_rn(oz, ow);
    ((__nv_bfloat162*)(bout + (size_t)node * CHID))[lane * 2] = lo;
    ((__nv_bfloat162*)(bout + (size_t)node * CHID))[lane * 2 + 1] = hi;
}

// ------- CSR gather + finalize, 64ch (no relu): one warp per node -------
__global__ void k_gather64(const int* __restrict__ rp, const int* __restrict__ cnt,
                           const int* __restrict__ csr, const float* __restrict__ z0,
                           const float* __restrict__ dinv, const float* __restrict__ invdeg,
                           const float* __restrict__ b, __nv_bfloat16* __restrict__ bout) {
    int warp = (blockIdx.x * blockDim.x + threadIdx.x) >> 5;
    int lane = threadIdx.x & 31;
    if (warp >= NN) return;
    int node = warp;
    int n = cnt[node];
    int base = rp[node];
    float dd = dinv[node];
    float2 acc = make_float2(0.f, 0.f);
    int j = 0;
    for (; j + 2 <= n; j += 2) {
        int s0 = csr[base + j];
        int s1 = csr[base + j + 1];
        float w0 = dinv[s0] * dd;
        float w1 = dinv[s1] * dd;
        float2 v0 = ((const float2*)(z0 + (size_t)s0 * COUT))[lane];
        float2 v1 = ((const float2*)(z0 + (size_t)s1 * COUT))[lane];
        acc.x += v0.x * w0 + v1.x * w1;
        acc.y += v0.y * w0 + v1.y * w1;
    }
    if (j < n) {
        int s0 = csr[base + j];
        float w0 = dinv[s0] * dd;
        float2 v0 = ((const float2*)(z0 + (size_t)s0 * COUT))[lane];
        acc.x += v0.x * w0; acc.y += v0.y * w0;
    }
    float idg = invdeg[node];
    float2 p = ((const float2*)(z0 + (size_t)node * COUT))[lane];
    float2 bv = ((const float2*)b)[lane];
    float ox = fmaf(p.x, idg, acc.x) + bv.x;
    float oy = fmaf(p.y, idg, acc.y) + bv.y;
    __nv_bfloat162 o2 = __floats2bfloat162_rn(ox, oy);
    ((__nv_bfloat162*)(bout + (size_t)node * COUT))[lane] = o2;
}

// ------- decode: out[e] = sigmoid(dot(ub[src], zb[dst]) + bb), 8 lanes/edge -------
__global__ void k_edges(const void* __restrict__ ei, const __nv_bfloat16* __restrict__ ub,
                        const __nv_bfloat16* __restrict__ zb, const float* __restrict__ bb,
                        float* __restrict__ out, const int* __restrict__ is64p) {
    unsigned t = blockIdx.x * blockDim.x + threadIdx.x;
    unsigned e = t >> 3;
    int lane = t & 7;
    if (e >= NE) return;
    int is64 = *is64p;
    int s = eidx(ei, e, is64);
    int d = eidx(ei, NE + e, is64);
    const __nv_bfloat162* ap = (const __nv_bfloat162*)(ub + (size_t)s * COUT) + lane * 4;
    const __nv_bfloat162* bp = (const __nv_bfloat162*)(zb + (size_t)d * COUT) + lane * 4;
    float p = 0.f;
#pragma unroll
    for (int j = 0; j < 4; j++) {
        float2 fa = __bfloat1622float2(ap[j]);
        float2 fb = __bfloat1622float2(bp[j]);
        p = fmaf(fa.x, fb.x, p);
        p = fmaf(fa.y, fb.y, p);
    }
    p += __shfl_xor_sync(0xffffffffu, p, 4);
    p += __shfl_xor_sync(0xffffffffu, p, 2);
    p += __shfl_xor_sync(0xffffffffu, p, 1);
    if (lane == 0) out[e] = 1.f / (1.f + expf(-(p + bb[0])));
}

extern "C" void kernel_launch(void* const* d_in, const int* in_sizes, int n_in,
                              void* d_out, int out_size) {
    const float* x  = (const float*)d_in[0];
    const void* ei  = d_in[1];
    const float* W1 = (const float*)d_in[2];
    const float* b1 = (const float*)d_in[3];
    const float* W2 = (const float*)d_in[4];
    const float* b2 = (const float*)d_in[5];
    const float* Wb = (const float*)d_in[6];
    const float* bb = (const float*)d_in[7];
    float* out      = (float*)d_out;

    int *cnt, *fpos, *tmp, *bsum, *rp, *csr, *is64p;
    float *dinv, *invdeg, *hW, *z0, *u;
    __nv_bfloat16 *xb, *W1b, *W2b, *Wbb, *hb, *zb, *ub;
    cudaGetSymbolAddress((void**)&cnt,   g_cnt);
    cudaGetSymbolAddress((void**)&fpos,  g_fpos);
    cudaGetSymbolAddress((void**)&tmp,   g_tmp);
    cudaGetSymbolAddress((void**)&bsum,  g_bsum);
    cudaGetSymbolAddress((void**)&rp,    g_rp);
    cudaGetSymbolAddress((void**)&csr,   g_csr);
    cudaGetSymbolAddress((void**)&dinv,  g_dinv);
    cudaGetSymbolAddress((void**)&invdeg,g_invdeg);
    cudaGetSymbolAddress((void**)&xb,    g_xb);
    cudaGetSymbolAddress((void**)&W1b,   g_W1b);
    cudaGetSymbolAddress((void**)&W2b,   g_W2b);
    cudaGetSymbolAddress((void**)&Wbb,   g_Wbb);
    cudaGetSymbolAddress((void**)&hW,    g_hW);
    cudaGetSymbolAddress((void**)&hb,    g_hb);
    cudaGetSymbolAddress((void**)&z0,    g_z0);
    cudaGetSymbolAddress((void**)&zb,    g_zb);
    cudaGetSymbolAddress((void**)&u,     g_u);
    cudaGetSymbolAddress((void**)&ub,    g_ub);
    cudaGetSymbolAddress((void**)&is64p, g_is64);

    const int T = 256;
    k_setup<<<(NN + T - 1) / T, T>>>((const int*)ei, cnt, fpos, is64p);
    k_count<<<(NE + T - 1) / T, T>>>(ei, cnt, is64p);
    k_dinv<<<(NN + T - 1) / T, T>>>(cnt, dinv, invdeg);
    k_scan1<<<NB, 256>>>(cnt, tmp, bsum);
    k_scan2<<<1, 256>>>(bsum);
    k_scan3<<<NB, 256>>>(tmp, bsum, rp);
    k_fill<<<(NE + T - 1) / T, T>>>(ei, rp, fpos, csr, is64p);
    k_cvt8<<<(NN_PAD * CIN / 8 + T - 1) / T, T>>>(x, xb, NN * CIN, NN_PAD * CIN);
    k_cvtW<<<(CIN * CHID + T - 1) / T, T>>>(W1, W2, Wb, W1b, W2b, Wbb);

    // conv1: GEMM + fused CSR gather/finalize -> bf16
    k_wgemm<CIN, CHID><<<NN_PAD / 64, 128>>>(xb, W1b, hW);
    k_gather128<<<(NN * 32 + T - 1) / T, T>>>(rp, cnt, csr, hW, dinv, invdeg, b1, hb);

    // conv2
    k_wgemm<CHID, COUT><<<NN_PAD / 64, 128>>>(hb, W2b, z0);
    k_gather64<<<(NN * 32 + T - 1) / T, T>>>(rp, cnt, csr, z0, dinv, invdeg, b2, zb);

    // decoder
    k_wgemm<COUT, COUT><<<NN_PAD / 64, 128>>>(zb, Wbb, u);
    k_cvt8<<<(NN_PAD * COUT / 8 + T - 1) / T, T>>>(u, ub, NN_PAD * COUT, NN_PAD * COUT);
    k_edges<<<(NE * 8 + T - 1) / T, T>>>(ei, ub, zb, bb, out, is64p);
}